// round 13
// baseline (speedup 1.0000x reference)
#include <cuda_runtime.h>
#include <cstddef>

// SpecialFlatten == batched float2 transpose: in2 [B, R, CP] -> out2 [B, CP, R]
// B=32, R=2048, C=512, CP=256.
//
// v13: v9's 32Rx32CP stage shape WITHOUT the pipeline — smallest per-CTA
// LDG front-batch of any variant (2x LDG.128/thread), 256 threads, 8.4KB smem,
// full residency. v9 measured the session-best DRAM 74.9% with this stage;
// this isolates the stage shape from the pipeline's register cost.
//
// Smem: even rows -> sA[m][.], odd rows -> sB[m][.] (m = pair 0..15),
// permuted columns s(c) = (c>>1) + (c&1)*16 => all STS.64/LDS.64 lane-linear.

namespace {
constexpr int B   = 32;
constexpr int R   = 2048;
constexpr int CP  = 256;           // float2 columns
constexpr int C4  = CP / 2;        // 128 float4 per input row
constexpr int R4  = R / 2;         // 1024 float4 per output row
constexpr int TILE_R = 32;         // float2 rows per tile (16 pairs)
constexpr int TILE_C = 32;         // float2 cols per tile (= 16 float4)
}

__global__ __launch_bounds__(256)
void special_flatten_v13(const float4* __restrict__ in,
                         float4* __restrict__ out) {
    __shared__ float2 sA[16][33];   // even rows (row 2m -> sA[m])
    __shared__ float2 sB[16][33];   // odd rows  (row 2m+1 -> sB[m])

    const int b = blockIdx.z;
    const float4* __restrict__ inb  = in  + (size_t)b * R * C4;
    float4* __restrict__       outb = out + (size_t)b * CP * R4;

    const int tid   = threadIdx.x;
    const int rtile = blockIdx.x;   // R-tile index (fastest-varying)
    const int ctile = blockIdx.y;   // CP-tile index

    // ---- Load phase: 2x LDG.128 per thread, STS.64 lane-linear ----
    {
        const int tx = tid & 15;                 // float4 col within tile (0..15)
        const int ty = tid >> 4;                 // row pair (0..15)
        const int c4 = ctile * (TILE_C / 2) + tx;
        const int r0 = rtile * TILE_R;
        const float4 v0 = inb[(size_t)(r0 + 2 * ty    ) * C4 + c4];
        const float4 v1 = inb[(size_t)(r0 + 2 * ty + 1) * C4 + c4];
        // logical cols 2tx, 2tx+1 -> storage cols tx, tx+16 (permuted)
        sA[ty][tx]      = make_float2(v0.x, v0.y);
        sA[ty][tx + 16] = make_float2(v0.z, v0.w);
        sB[ty][tx]      = make_float2(v1.x, v1.y);
        sB[ty][tx + 16] = make_float2(v1.z, v1.w);
    }

    __syncthreads();

    // ---- Store phase: LDS.64 lane-linear, 2x STG.128 per thread ----
    {
        const int sx = tid & 15;                 // float4 R-index within tile (0..15)
        const int sy = tid >> 4;                 // 0..15
        const int r4 = rtile * (TILE_R / 2) + sx;
#pragma unroll
        for (int n = 0; n < 2; n++) {
            const int c  = sy + 16 * n;          // CP-local col 0..31
            const int sc = (c >> 1) + (c & 1) * 16;   // permuted storage col
            const float2 a  = sA[sx][sc];        // in2[2*sx][c]
            const float2 bb = sB[sx][sc];        // in2[2*sx+1][c]
            outb[(size_t)(ctile * TILE_C + c) * R4 + r4] =
                make_float4(a.x, a.y, bb.x, bb.y);
        }
    }
}

extern "C" void kernel_launch(void* const* d_in, const int* in_sizes, int n_in,
                              void* d_out, int out_size) {
    const float4* in  = (const float4*)d_in[0];
    float4*       out = (float4*)d_out;

    dim3 block(256, 1, 1);
    dim3 grid(R / TILE_R, CP / TILE_C, B);   // (64, 8, 32) = 16384 blocks
    special_flatten_v13<<<grid, block>>>(in, out);
}